// round 3
// baseline (speedup 1.0000x reference)
#include <cuda_runtime.h>
#include <math.h>

#define PI_F 3.14159265358979323846f

// Precomputed per-launch circuit data (written by setup_kernel, read by qc_kernel)
__device__ float2 g_Uq[16][16];   // [col j][row i] : column j = U_q applied to basis state e_j
__device__ float2 g_Uv[16][16];
__device__ float  g_kx[4];        // <X_w> of the fixed k-register state

// ---------- complex helpers ----------
__device__ __forceinline__ float2 cmul(float2 a, float2 b){
    return make_float2(a.x*b.x - a.y*b.y, a.x*b.y + a.y*b.x);
}
__device__ __forceinline__ float2 cadd(float2 a, float2 b){ return make_float2(a.x+b.x, a.y+b.y); }
__device__ __forceinline__ float2 expi(float a){ float s,c; sincosf(a,&s,&c); return make_float2(c,s); }
__device__ __forceinline__ float2 cscale(float2 a, float s){ return make_float2(a.x*s, a.y*s); }
__device__ __forceinline__ float2 shflx(float2 v, int m){
    return make_float2(__shfl_xor_sync(0xffffffffu, v.x, m),
                       __shfl_xor_sync(0xffffffffu, v.y, m));
}

// ---------- setup: build U_q, U_v columns and k-state X expectations ----------
// 34 groups of 16 lanes (one amplitude per lane, one circuit per group):
//   groups 0-15  : U_q columns
//   groups 16-31 : U_v columns
//   group  32    : k circuit on |0000>  -> g_kx
//   group  33    : dummy (keeps last warp full for shfl masks)
__global__ void setup_kernel(const float* __restrict__ qr, const float* __restrict__ kr,
                             const float* __restrict__ vr, const float* __restrict__ qc,
                             const float* __restrict__ kc, const float* __restrict__ vc)
{
    int t    = threadIdx.x;        // 0..543
    int grp  = t >> 4;
    int lane = t & 15;             // amplitude index (wire0 = MSB: mask = 8>>w)

    const float* rot; const float* crx; int col;
    if (grp < 16)      { rot = qr; crx = qc; col = grp;      }
    else if (grp < 32) { rot = vr; crx = vc; col = grp - 16; }
    else               { rot = kr; crx = kc; col = 0;        }

    float2 s = (lane == col) ? make_float2(1.f, 0.f) : make_float2(0.f, 0.f);

    const int pa[8] = {0,1,2,3,0,1,2,3};
    const int pb[8] = {1,2,3,0,3,0,1,2};

    #pragma unroll 1
    for (int g = 0; g < 8; g++){
        int ma = 8 >> pa[g], mb = 8 >> pb[g];

        // Rot(phi, th, om) on wire a
        float phi = rot[3*g], th = rot[3*g+1], om = rot[3*g+2];
        float c, sn; sincosf(0.5f*th, &sn, &c);
        float2 u00 = cscale(expi(-0.5f*(phi+om)),  c);
        float2 u01 = cscale(expi( 0.5f*(phi-om)), -sn);
        float2 u10 = cscale(expi(-0.5f*(phi-om)),  sn);
        float2 u11 = cscale(expi( 0.5f*(phi+om)),  c);
        float2 o = shflx(s, ma);
        s = (lane & ma) ? cadd(cmul(u10, o), cmul(u11, s))
                        : cadd(cmul(u00, s), cmul(u01, o));

        // CRX(t) control a, target b  (RX is symmetric: new = c*mine - i*s*other)
        float tt = crx[g];
        float cc, ss; sincosf(0.5f*tt, &ss, &cc);
        o = shflx(s, mb);
        if (lane & ma) s = make_float2(cc*s.x + ss*o.y, cc*s.y - ss*o.x);

        // CNOT(a, b)
        o = shflx(s, mb);
        if (lane & ma) s = o;
    }

    if (grp < 16)       g_Uq[grp][lane]      = s;
    else if (grp < 32)  g_Uv[grp - 16][lane] = s;
    else {
        // <X_w> = sum_i Re(conj(s_i) s_{i^mask})  (both groups of warp 16 participate in shfls)
        #pragma unroll
        for (int w = 0; w < 4; w++){
            int m = 8 >> w;
            float2 o = shflx(s, m);
            float v = s.x*o.x + s.y*o.y;
            v += __shfl_xor_sync(0xffffffffu, v, 1);
            v += __shfl_xor_sync(0xffffffffu, v, 2);
            v += __shfl_xor_sync(0xffffffffu, v, 4);
            v += __shfl_xor_sync(0xffffffffu, v, 8);
            if (grp == 32 && lane == 0) g_kx[w] = v;
        }
    }
}

// ---------- per-sample 16x16 matvec exploiting product-state structure ----------
// p_j = m_j * (-i)^popc(j); sign of (-1) folded into m_j, so:
//   popc even: out_i += U[i][j] * m_j
//   popc odd : out_i += (-i) * U[i][j] * m_j
__device__ __forceinline__ void matvec16(const float4* __restrict__ U, const float* m, float2* st){
    #pragma unroll
    for (int i = 0; i < 16; i++) st[i] = make_float2(0.f, 0.f);
    #pragma unroll
    for (int j = 0; j < 16; j++){
        float mj = m[j];
        if ((0x6996 >> j) & 1){            // odd parity: multiply by -i
            #pragma unroll
            for (int i = 0; i < 16; i += 2){
                float4 u = U[j*8 + (i >> 1)];
                st[i  ].x += u.y*mj;  st[i  ].y -= u.x*mj;
                st[i+1].x += u.w*mj;  st[i+1].y -= u.z*mj;
            }
        } else {
            #pragma unroll
            for (int i = 0; i < 16; i += 2){
                float4 u = U[j*8 + (i >> 1)];
                st[i  ].x += u.x*mj;  st[i  ].y += u.y*mj;
                st[i+1].x += u.z*mj;  st[i+1].y += u.w*mj;
            }
        }
    }
}

__global__ void __launch_bounds__(128)
qc_kernel(const float* __restrict__ x1, const float* __restrict__ pre_w,
          const float* __restrict__ pre_b,
          const float* __restrict__ ln_w, const float* __restrict__ ln_b,
          const float* __restrict__ head_w, const float* __restrict__ head_b,
          float* __restrict__ out, int B)
{
    __shared__ float4 sUq[128];   // 16x16 complex = 256 float2 = 128 float4
    __shared__ float4 sUv[128];
    __shared__ float  sW[384];
    __shared__ float  sKx[4];
    __shared__ float  sPB[4];

    for (int i = threadIdx.x; i < 128; i += blockDim.x){
        sUq[i] = ((const float4*)g_Uq)[i];
        sUv[i] = ((const float4*)g_Uv)[i];
    }
    for (int i = threadIdx.x; i < 384; i += blockDim.x) sW[i] = pre_w[i];
    if (threadIdx.x < 4){ sKx[threadIdx.x] = g_kx[threadIdx.x]; sPB[threadIdx.x] = pre_b[threadIdx.x]; }
    __syncthreads();

    int tid = blockIdx.x * blockDim.x + threadIdx.x;
    if (tid >= B) return;

    // ---- x = x1[tid] @ pre_w.T + pre_b ----
    float a0 = 0.f, a1 = 0.f, a2 = 0.f, a3 = 0.f;
    const float4* row = (const float4*)(x1 + (size_t)tid * 96);
    #pragma unroll
    for (int k = 0; k < 24; k++){
        float4 v = row[k];
        a0 += v.x*sW[      4*k] + v.y*sW[      4*k+1] + v.z*sW[      4*k+2] + v.w*sW[      4*k+3];
        a1 += v.x*sW[ 96 + 4*k] + v.y*sW[ 96 + 4*k+1] + v.z*sW[ 96 + 4*k+2] + v.w*sW[ 96 + 4*k+3];
        a2 += v.x*sW[192 + 4*k] + v.y*sW[192 + 4*k+1] + v.z*sW[192 + 4*k+2] + v.w*sW[192 + 4*k+3];
        a3 += v.x*sW[288 + 4*k] + v.y*sW[288 + 4*k+1] + v.z*sW[288 + 4*k+2] + v.w*sW[288 + 4*k+3];
    }
    float xw[4] = { a0 + sPB[0], a1 + sPB[1], a2 + sPB[2], a3 + sPB[3] };

    // half-angle sin/cos of embedding RX gates
    float hc[4], hs[4];
    #pragma unroll
    for (int w = 0; w < 4; w++) sincosf(0.5f * xw[w], &hs[w], &hc[w]);

    // product state p = RX(x)|0000> : magnitudes with (-1) of the (-i)^popc folded in
    float m[16];
    #pragma unroll
    for (int i = 0; i < 16; i++){
        float v = ((i&8)?hs[0]:hc[0]) * ((i&4)?hs[1]:hc[1]) * ((i&2)?hs[2]:hc[2]) * ((i&1)?hs[3]:hc[3]);
        int pc = __popc(i);
        m[i] = (pc & 2) ? -v : v;
    }

    float2 st[16];

    // ---- q register: psi_q = RX(x) * U_q * p ----
    matvec16(sUq, m, st);
    #pragma unroll
    for (int w = 0; w < 4; w++){
        int mm = 8 >> w;
        float c = hc[w], s = hs[w];
        #pragma unroll
        for (int i = 0; i < 16; i++){
            if (i & mm) continue;
            float2 a = st[i], b = st[i | mm];
            st[i]      = make_float2(c*a.x + s*b.y,  c*a.y - s*b.x);
            st[i | mm] = make_float2(s*a.y + c*b.x, -s*a.x + c*b.y);
        }
    }

    // scores: z_w = <Z_w>_q ; xm_w = <X_w>_q * kx_w  (CNOT layer commuted into observables)
    float rz[4];
    #pragma unroll
    for (int w = 0; w < 4; w++){
        int mm = 8 >> w;
        float z = 0.f, xm = 0.f;
        #pragma unroll
        for (int i = 0; i < 16; i++){
            float n = st[i].x*st[i].x + st[i].y*st[i].y;
            z += (i & mm) ? -n : n;
        }
        #pragma unroll
        for (int i = 0; i < 16; i++){
            if (i & mm) continue;
            xm += st[i].x*st[i|mm].x + st[i].y*st[i|mm].y;
        }
        xm = 2.f * xm * sKx[w];
        float sc = sqrtf(z*z + xm*xm);
        rz[w] = tanhf(sc) * (0.5f * PI_F);   // RZ half-angle
    }

    // ---- value register: phi = CNOTchain * RZ(angles) * U_v * p ----
    matvec16(sUv, m, st);
    #pragma unroll
    for (int i = 0; i < 16; i++){
        float ph = ((i&8)?rz[0]:-rz[0]) + ((i&4)?rz[1]:-rz[1])
                 + ((i&2)?rz[2]:-rz[2]) + ((i&1)?rz[3]:-rz[3]);
        float sp, cp; __sincosf(ph, &sp, &cp);
        st[i] = make_float2(st[i].x*cp - st[i].y*sp, st[i].x*sp + st[i].y*cp);
    }
    // CNOT(0,1), CNOT(1,2), CNOT(2,3)  (pure register permutations after unroll)
    #pragma unroll
    for (int i = 0; i < 16; i++){
        if ((i & 8) && !(i & 4)){ float2 t = st[i]; st[i] = st[i|4]; st[i|4] = t; }
    }
    #pragma unroll
    for (int i = 0; i < 16; i++){
        if ((i & 4) && !(i & 2)){ float2 t = st[i]; st[i] = st[i|2]; st[i|2] = t; }
    }
    #pragma unroll
    for (int i = 0; i < 16; i++){
        if ((i & 2) && !(i & 1)){ float2 t = st[i]; st[i] = st[i|1]; st[i|1] = t; }
    }

    // outs = [zv0..3, xv0..3]
    float o[8];
    #pragma unroll
    for (int w = 0; w < 4; w++){
        int mm = 8 >> w;
        float z = 0.f, xv = 0.f;
        #pragma unroll
        for (int i = 0; i < 16; i++){
            float n = st[i].x*st[i].x + st[i].y*st[i].y;
            z += (i & mm) ? -n : n;
        }
        #pragma unroll
        for (int i = 0; i < 16; i++){
            if (i & mm) continue;
            xv += st[i].x*st[i|mm].x + st[i].y*st[i|mm].y;
        }
        o[w]     = z;
        o[4 + w] = 2.f * xv;
    }

    // LayerNorm(8) -> GELU(erf) -> head [2x8]
    float mu = 0.f;
    #pragma unroll
    for (int k = 0; k < 8; k++) mu += o[k];
    mu *= 0.125f;
    float var = 0.f;
    #pragma unroll
    for (int k = 0; k < 8; k++){ float d = o[k] - mu; var += d * d; }
    var *= 0.125f;
    float inv = rsqrtf(var + 1e-5f);

    float r0 = __ldg(&head_b[0]);
    float r1 = __ldg(&head_b[1]);
    #pragma unroll
    for (int k = 0; k < 8; k++){
        float y = (o[k] - mu) * inv * __ldg(&ln_w[k]) + __ldg(&ln_b[k]);
        float g = 0.5f * y * (1.f + erff(y * 0.70710678118654752f));
        r0 += g * __ldg(&head_w[k]);
        r1 += g * __ldg(&head_w[8 + k]);
    }
    ((float2*)out)[tid] = make_float2(r0, r1);
}

extern "C" void kernel_launch(void* const* d_in, const int* in_sizes, int n_in,
                              void* d_out, int out_size)
{
    const float* x1     = (const float*)d_in[0];
    const float* pre_w  = (const float*)d_in[1];
    const float* pre_b  = (const float*)d_in[2];
    const float* q_rot  = (const float*)d_in[3];
    const float* k_rot  = (const float*)d_in[4];
    const float* v_rot  = (const float*)d_in[5];
    const float* q_crx  = (const float*)d_in[6];
    const float* k_crx  = (const float*)d_in[7];
    const float* v_crx  = (const float*)d_in[8];
    const float* ln_w   = (const float*)d_in[9];
    const float* ln_b   = (const float*)d_in[10];
    const float* head_w = (const float*)d_in[11];
    const float* head_b = (const float*)d_in[12];

    int B = in_sizes[0] / 96;

    setup_kernel<<<1, 544>>>(q_rot, k_rot, v_rot, q_crx, k_crx, v_crx);
    qc_kernel<<<(B + 127) / 128, 128>>>(x1, pre_w, pre_b, ln_w, ln_b, head_w, head_b,
                                        (float*)d_out, B);
}

// round 5
// speedup vs baseline: 1.0935x; 1.0935x over previous
#include <cuda_runtime.h>
#include <math.h>

#define PI_F 3.14159265358979323846f

__device__ __forceinline__ float2 cmul(float2 a, float2 b){
    return make_float2(a.x*b.x - a.y*b.y, a.x*b.y + a.y*b.x);
}
__device__ __forceinline__ float2 cadd(float2 a, float2 b){ return make_float2(a.x+b.x, a.y+b.y); }
__device__ __forceinline__ float2 expi(float a){ float s,c; __sincosf(a,&s,&c); return make_float2(c,s); }
__device__ __forceinline__ float2 cscale(float2 a, float s){ return make_float2(a.x*s, a.y*s); }
__device__ __forceinline__ float2 shflx(float2 v, int m){
    return make_float2(__shfl_xor_sync(0xffffffffu, v.x, m),
                       __shfl_xor_sync(0xffffffffu, v.y, m));
}
__device__ __forceinline__ float fast_tanh(float x){
    // x >= 0 here
    float e = __expf(2.f * x);
    return 1.f - 2.f / (e + 1.f);
}

// simulate the 8-gate initQKV circuit on 16 amplitudes held across a 16-lane segment
__device__ __forceinline__ float2 sim16(const float* rot, const float* crx, int col, int lane)
{
    float2 s = (lane == col) ? make_float2(1.f, 0.f) : make_float2(0.f, 0.f);
    const int pa[8] = {0,1,2,3,0,1,2,3};
    const int pb[8] = {1,2,3,0,3,0,1,2};
    #pragma unroll 1
    for (int g = 0; g < 8; g++){
        int ma = 8 >> pa[g], mb = 8 >> pb[g];
        float phi = rot[3*g], th = rot[3*g+1], om = rot[3*g+2];
        float c, sn; __sincosf(0.5f*th, &sn, &c);
        float2 u00 = cscale(expi(-0.5f*(phi+om)),  c);
        float2 u01 = cscale(expi( 0.5f*(phi-om)), -sn);
        float2 u10 = cscale(expi(-0.5f*(phi-om)),  sn);
        float2 u11 = cscale(expi( 0.5f*(phi+om)),  c);
        float2 o = shflx(s, ma);
        s = (lane & ma) ? cadd(cmul(u10, o), cmul(u11, s))
                        : cadd(cmul(u00, s), cmul(u01, o));
        float tt = crx[g];
        float cc, ss; __sincosf(0.5f*tt, &ss, &cc);
        o = shflx(s, mb);
        if (lane & ma) s = make_float2(cc*s.x + ss*o.y, cc*s.y - ss*o.x);
        o = shflx(s, mb);
        if (lane & ma) s = o;
    }
    return s;
}

__global__ void __launch_bounds__(256)
qc_kernel(const float* __restrict__ x1, const float* __restrict__ pre_w,
          const float* __restrict__ pre_b,
          const float* __restrict__ q_rot, const float* __restrict__ k_rot,
          const float* __restrict__ v_rot,
          const float* __restrict__ q_crx, const float* __restrict__ k_crx,
          const float* __restrict__ v_crx,
          const float* __restrict__ ln_w, const float* __restrict__ ln_b,
          const float* __restrict__ head_w, const float* __restrict__ head_b,
          float* __restrict__ out, int B)
{
    __shared__ float2 sUq[256];   // [col*16 + row]
    __shared__ float2 sUv[256];
    __shared__ float  sW[384];    // pre_w row-major [4][96]
    __shared__ float  sKx[4];
    __shared__ float  sPB[4];
    __shared__ float  sLnW[8], sLnB[8], sHW[16], sHB[2];

    int t = threadIdx.x;

    // ---- per-block setup: small params + circuit unitaries ----
    for (int i = t; i < 384; i += 256) sW[i] = pre_w[i];   // FIX: strided, covers all 384
    if (t < 4)  { sPB[t] = pre_b[t]; }
    if (t >= 4 && t < 12)   sLnW[t-4]  = ln_w[t-4];
    if (t >= 12 && t < 20)  sLnB[t-12] = ln_b[t-12];
    if (t >= 20 && t < 36)  sHW[t-20]  = head_w[t-20];
    if (t >= 36 && t < 38)  sHB[t-36]  = head_b[t-36];

    {
        int grp  = t >> 4;      // 0..15
        int lane = t & 15;
        float2 uq = sim16(q_rot, q_crx, grp, lane);
        sUq[grp*16 + lane] = uq;
        float2 uv = sim16(v_rot, v_crx, grp, lane);
        sUv[grp*16 + lane] = uv;
        float2 ks = sim16(k_rot, k_crx, 0, lane);   // all groups identical
        #pragma unroll
        for (int w = 0; w < 4; w++){
            int mmk = 8 >> w;
            float2 o = shflx(ks, mmk);
            float v = ks.x*o.x + ks.y*o.y;
            v += __shfl_xor_sync(0xffffffffu, v, 1);
            v += __shfl_xor_sync(0xffffffffu, v, 2);
            v += __shfl_xor_sync(0xffffffffu, v, 4);
            v += __shfl_xor_sync(0xffffffffu, v, 8);
            if (grp == 0 && lane == 0) sKx[w] = v;
        }
    }
    __syncthreads();

    // ---- main phase: 4 lanes per sample ----
    int s_idx = blockIdx.x * 64 + (t >> 2);
    int l     = t & 3;                       // quad lane: rows 4l..4l+3
    if (s_idx >= B) return;

    const float4* sW4  = (const float4*)sW;
    const float4* sUq4 = (const float4*)sUq;
    const float4* sUv4 = (const float4*)sUv;

    // x = x1[s] @ pre_w.T + pre_b  (each lane does 24 of 96, butterfly-reduce)
    float a0 = 0.f, a1 = 0.f, a2 = 0.f, a3 = 0.f;
    {
        const float4* row = (const float4*)(x1 + (size_t)s_idx * 96) + l * 6;
        #pragma unroll
        for (int k = 0; k < 6; k++){
            float4 v = row[k];
            float4 w0 = sW4[      l*6 + k];
            float4 w1 = sW4[ 24 + l*6 + k];
            float4 w2 = sW4[ 48 + l*6 + k];
            float4 w3 = sW4[ 72 + l*6 + k];
            a0 += v.x*w0.x + v.y*w0.y + v.z*w0.z + v.w*w0.w;
            a1 += v.x*w1.x + v.y*w1.y + v.z*w1.z + v.w*w1.w;
            a2 += v.x*w2.x + v.y*w2.y + v.z*w2.z + v.w*w2.w;
            a3 += v.x*w3.x + v.y*w3.y + v.z*w3.z + v.w*w3.w;
        }
        #pragma unroll
        for (int d = 1; d <= 2; d <<= 1){
            a0 += __shfl_xor_sync(0xffffffffu, a0, d);
            a1 += __shfl_xor_sync(0xffffffffu, a1, d);
            a2 += __shfl_xor_sync(0xffffffffu, a2, d);
            a3 += __shfl_xor_sync(0xffffffffu, a3, d);
        }
    }
    float xw[4] = { a0 + sPB[0], a1 + sPB[1], a2 + sPB[2], a3 + sPB[3] };

    float hc[4], hs[4];
    #pragma unroll
    for (int w = 0; w < 4; w++) __sincosf(0.5f * xw[w], &hs[w], &hc[w]);

    // product state magnitudes, (-1) of (-i)^popc folded in
    float m[16];
    #pragma unroll
    for (int i = 0; i < 16; i++){
        float v = ((i&8)?hs[0]:hc[0]) * ((i&4)?hs[1]:hc[1]) * ((i&2)?hs[2]:hc[2]) * ((i&1)?hs[3]:hc[3]);
        m[i] = (__popc(i) & 2) ? -v : v;
    }

    // ---- both matvecs (rows 4l..4l+3 of U_q*p and U_v*p) ----
    float2 stq[4], stv[4];
    #pragma unroll
    for (int r = 0; r < 4; r++){ stq[r] = make_float2(0.f,0.f); stv[r] = make_float2(0.f,0.f); }
    #pragma unroll
    for (int j = 0; j < 16; j++){
        float mj = m[j];
        float4 q0 = sUq4[j*8 + 2*l], q1 = sUq4[j*8 + 2*l + 1];
        float4 v0 = sUv4[j*8 + 2*l], v1 = sUv4[j*8 + 2*l + 1];
        if ((0x6996 >> j) & 1){   // odd parity: * (-i)
            stq[0].x += q0.y*mj; stq[0].y -= q0.x*mj;
            stq[1].x += q0.w*mj; stq[1].y -= q0.z*mj;
            stq[2].x += q1.y*mj; stq[2].y -= q1.x*mj;
            stq[3].x += q1.w*mj; stq[3].y -= q1.z*mj;
            stv[0].x += v0.y*mj; stv[0].y -= v0.x*mj;
            stv[1].x += v0.w*mj; stv[1].y -= v0.z*mj;
            stv[2].x += v1.y*mj; stv[2].y -= v1.x*mj;
            stv[3].x += v1.w*mj; stv[3].y -= v1.z*mj;
        } else {
            stq[0].x += q0.x*mj; stq[0].y += q0.y*mj;
            stq[1].x += q0.z*mj; stq[1].y += q0.w*mj;
            stq[2].x += q1.x*mj; stq[2].y += q1.y*mj;
            stq[3].x += q1.z*mj; stq[3].y += q1.w*mj;
            stv[0].x += v0.x*mj; stv[0].y += v0.y*mj;
            stv[1].x += v0.z*mj; stv[1].y += v0.w*mj;
            stv[2].x += v1.x*mj; stv[2].y += v1.y*mj;
            stv[3].x += v1.z*mj; stv[3].y += v1.w*mj;
        }
    }

    // ---- q path: RX(x) layer. RX pair-update is symmetric: new = (c*m.x + s*o.y, c*m.y - s*o.x)
    // wire0 (bit3): partner lane l^2 ; wire1 (bit2): partner lane l^1
    #pragma unroll
    for (int w = 0; w < 2; w++){
        int d = 2 >> w;   // 2 then 1
        float c = hc[w], s = hs[w];
        #pragma unroll
        for (int r = 0; r < 4; r++){
            float2 o = shflx(stq[r], d);
            stq[r] = make_float2(c*stq[r].x + s*o.y, c*stq[r].y - s*o.x);
        }
    }
    {   // wire2 (bit1): rows r <-> r^2
        float c = hc[2], s = hs[2];
        float2 n0 = make_float2(c*stq[0].x + s*stq[2].y, c*stq[0].y - s*stq[2].x);
        float2 n2 = make_float2(c*stq[2].x + s*stq[0].y, c*stq[2].y - s*stq[0].x);
        float2 n1 = make_float2(c*stq[1].x + s*stq[3].y, c*stq[1].y - s*stq[3].x);
        float2 n3 = make_float2(c*stq[3].x + s*stq[1].y, c*stq[3].y - s*stq[1].x);
        stq[0]=n0; stq[1]=n1; stq[2]=n2; stq[3]=n3;
    }
    {   // wire3 (bit0): rows r <-> r^1
        float c = hc[3], s = hs[3];
        float2 n0 = make_float2(c*stq[0].x + s*stq[1].y, c*stq[0].y - s*stq[1].x);
        float2 n1 = make_float2(c*stq[1].x + s*stq[0].y, c*stq[1].y - s*stq[0].x);
        float2 n2 = make_float2(c*stq[2].x + s*stq[3].y, c*stq[2].y - s*stq[3].x);
        float2 n3 = make_float2(c*stq[3].x + s*stq[2].y, c*stq[3].y - s*stq[2].x);
        stq[0]=n0; stq[1]=n1; stq[2]=n2; stq[3]=n3;
    }

    // ---- scores: z_w = <Z_w>, xm_w = <X_w> * kx_w (full sums over lanes) ----
    float n0 = stq[0].x*stq[0].x + stq[0].y*stq[0].y;
    float n1 = stq[1].x*stq[1].x + stq[1].y*stq[1].y;
    float n2 = stq[2].x*stq[2].x + stq[2].y*stq[2].y;
    float n3 = stq[3].x*stq[3].x + stq[3].y*stq[3].y;
    float nsum = n0 + n1 + n2 + n3;
    float z0 = (l & 2) ? -nsum : nsum;
    float z1 = (l & 1) ? -nsum : nsum;
    float z2 = n0 + n1 - n2 - n3;
    float z3 = n0 - n1 + n2 - n3;

    float x0 = 0.f, x1m = 0.f;
    #pragma unroll
    for (int r = 0; r < 4; r++){
        float2 o = shflx(stq[r], 2);
        x0 += stq[r].x*o.x + stq[r].y*o.y;
    }
    #pragma unroll
    for (int r = 0; r < 4; r++){
        float2 o = shflx(stq[r], 1);
        x1m += stq[r].x*o.x + stq[r].y*o.y;
    }
    float x2 = 2.f*(stq[0].x*stq[2].x + stq[0].y*stq[2].y + stq[1].x*stq[3].x + stq[1].y*stq[3].y);
    float x3 = 2.f*(stq[0].x*stq[1].x + stq[0].y*stq[1].y + stq[2].x*stq[3].x + stq[2].y*stq[3].y);

    // butterfly-reduce the 8 partials across the quad
    #pragma unroll
    for (int d = 1; d <= 2; d <<= 1){
        z0 += __shfl_xor_sync(0xffffffffu, z0, d);
        z1 += __shfl_xor_sync(0xffffffffu, z1, d);
        z2 += __shfl_xor_sync(0xffffffffu, z2, d);
        z3 += __shfl_xor_sync(0xffffffffu, z3, d);
        x0 += __shfl_xor_sync(0xffffffffu, x0, d);
        x1m+= __shfl_xor_sync(0xffffffffu, x1m, d);
        x2 += __shfl_xor_sync(0xffffffffu, x2, d);
        x3 += __shfl_xor_sync(0xffffffffu, x3, d);
    }
    x0 *= sKx[0]; x1m *= sKx[1]; x2 *= sKx[2]; x3 *= sKx[3];

    float rz0 = fast_tanh(sqrtf(z0*z0 + x0*x0))   * (0.5f * PI_F);
    float rz1 = fast_tanh(sqrtf(z1*z1 + x1m*x1m)) * (0.5f * PI_F);
    float rz2 = fast_tanh(sqrtf(z2*z2 + x2*x2))   * (0.5f * PI_F);
    float rz3 = fast_tanh(sqrtf(z3*z3 + x3*x3))   * (0.5f * PI_F);

    // ---- v path: RZ phases ----
    float phl = ((l & 2) ? rz0 : -rz0) + ((l & 1) ? rz1 : -rz1);
    #pragma unroll
    for (int r = 0; r < 4; r++){
        float ph = phl + ((r & 2) ? rz2 : -rz2) + ((r & 1) ? rz3 : -rz3);
        float sp, cp; __sincosf(ph, &sp, &cp);
        stv[r] = make_float2(stv[r].x*cp - stv[r].y*sp, stv[r].x*sp + stv[r].y*cp);
    }
    // CNOT(0,1): lanes 2,3 swap with partner lane (l^1)
    #pragma unroll
    for (int r = 0; r < 4; r++){
        float2 o = shflx(stv[r], 1);
        if (l & 2) stv[r] = o;
    }
    // CNOT(1,2): if bit2 (l&1): swap rows r <-> r^2
    if (l & 1){
        float2 tq = stv[0]; stv[0] = stv[2]; stv[2] = tq;
        tq = stv[1]; stv[1] = stv[3]; stv[3] = tq;
    }
    // CNOT(2,3): swap rows 2,3
    { float2 tq = stv[2]; stv[2] = stv[3]; stv[3] = tq; }

    // ---- final expectations ----
    float q0n = stv[0].x*stv[0].x + stv[0].y*stv[0].y;
    float q1n = stv[1].x*stv[1].x + stv[1].y*stv[1].y;
    float q2n = stv[2].x*stv[2].x + stv[2].y*stv[2].y;
    float q3n = stv[3].x*stv[3].x + stv[3].y*stv[3].y;
    float qs = q0n + q1n + q2n + q3n;
    float o0 = (l & 2) ? -qs : qs;
    float o1 = (l & 1) ? -qs : qs;
    float o2 = q0n + q1n - q2n - q3n;
    float o3 = q0n - q1n + q2n - q3n;

    float o4 = 0.f, o5 = 0.f;
    #pragma unroll
    for (int r = 0; r < 4; r++){
        float2 o = shflx(stv[r], 2);
        o4 += stv[r].x*o.x + stv[r].y*o.y;
    }
    #pragma unroll
    for (int r = 0; r < 4; r++){
        float2 o = shflx(stv[r], 1);
        o5 += stv[r].x*o.x + stv[r].y*o.y;
    }
    float o6 = 2.f*(stv[0].x*stv[2].x + stv[0].y*stv[2].y + stv[1].x*stv[3].x + stv[1].y*stv[3].y);
    float o7 = 2.f*(stv[0].x*stv[1].x + stv[0].y*stv[1].y + stv[2].x*stv[3].x + stv[2].y*stv[3].y);

    #pragma unroll
    for (int d = 1; d <= 2; d <<= 1){
        o0 += __shfl_xor_sync(0xffffffffu, o0, d);
        o1 += __shfl_xor_sync(0xffffffffu, o1, d);
        o2 += __shfl_xor_sync(0xffffffffu, o2, d);
        o3 += __shfl_xor_sync(0xffffffffu, o3, d);
        o4 += __shfl_xor_sync(0xffffffffu, o4, d);
        o5 += __shfl_xor_sync(0xffffffffu, o5, d);
        o6 += __shfl_xor_sync(0xffffffffu, o6, d);
        o7 += __shfl_xor_sync(0xffffffffu, o7, d);
    }

    if (l == 0){
        float o[8] = { o0, o1, o2, o3, o4, o5, o6, o7 };
        float mu = 0.f;
        #pragma unroll
        for (int k = 0; k < 8; k++) mu += o[k];
        mu *= 0.125f;
        float var = 0.f;
        #pragma unroll
        for (int k = 0; k < 8; k++){ float dd = o[k] - mu; var += dd * dd; }
        var *= 0.125f;
        float inv = rsqrtf(var + 1e-5f);

        float r0 = sHB[0], r1 = sHB[1];
        #pragma unroll
        for (int k = 0; k < 8; k++){
            float y = (o[k] - mu) * inv * sLnW[k] + sLnB[k];
            float g = 0.5f * y * (1.f + erff(y * 0.70710678118654752f));
            r0 += g * sHW[k];
            r1 += g * sHW[8 + k];
        }
        ((float2*)out)[s_idx] = make_float2(r0, r1);
    }
}

extern "C" void kernel_launch(void* const* d_in, const int* in_sizes, int n_in,
                              void* d_out, int out_size)
{
    const float* x1     = (const float*)d_in[0];
    const float* pre_w  = (const float*)d_in[1];
    const float* pre_b  = (const float*)d_in[2];
    const float* q_rot  = (const float*)d_in[3];
    const float* k_rot  = (const float*)d_in[4];
    const float* v_rot  = (const float*)d_in[5];
    const float* q_crx  = (const float*)d_in[6];
    const float* k_crx  = (const float*)d_in[7];
    const float* v_crx  = (const float*)d_in[8];
    const float* ln_w   = (const float*)d_in[9];
    const float* ln_b   = (const float*)d_in[10];
    const float* head_w = (const float*)d_in[11];
    const float* head_b = (const float*)d_in[12];

    int B = in_sizes[0] / 96;
    int blocks = (B + 63) / 64;

    qc_kernel<<<blocks, 256>>>(x1, pre_w, pre_b, q_rot, k_rot, v_rot,
                               q_crx, k_crx, v_crx, ln_w, ln_b, head_w, head_b,
                               (float*)d_out, B);
}

// round 6
// speedup vs baseline: 1.4147x; 1.2937x over previous
#include <cuda_runtime.h>
#include <math.h>

#define PI_F 3.14159265358979323846f

__device__ __forceinline__ float2 cmul(float2 a, float2 b){
    return make_float2(a.x*b.x - a.y*b.y, a.x*b.y + a.y*b.x);
}
__device__ __forceinline__ float2 cadd(float2 a, float2 b){ return make_float2(a.x+b.x, a.y+b.y); }
__device__ __forceinline__ float2 expi(float a){ float s,c; __sincosf(a,&s,&c); return make_float2(c,s); }
__device__ __forceinline__ float2 cscale(float2 a, float s){ return make_float2(a.x*s, a.y*s); }
__device__ __forceinline__ float2 shflx(float2 v, int m){
    return make_float2(__shfl_xor_sync(0xffffffffu, v.x, m),
                       __shfl_xor_sync(0xffffffffu, v.y, m));
}
__device__ __forceinline__ float fast_tanh(float x){
    float e = __expf(2.f * x);
    return 1.f - 2.f / (e + 1.f);
}

// simulate the 8-gate initQKV circuit on 16 amplitudes held across a 16-lane segment
// FULLY UNROLLED: gate wire masks become immediates, no local-memory arrays.
__device__ __forceinline__ float2 sim16(const float* __restrict__ rot,
                                        const float* __restrict__ crx,
                                        int col, int lane)
{
    float2 s = (lane == col) ? make_float2(1.f, 0.f) : make_float2(0.f, 0.f);
    #pragma unroll
    for (int g = 0; g < 8; g++){
        const int pa_[8] = {0,1,2,3,0,1,2,3};
        const int pb_[8] = {1,2,3,0,3,0,1,2};
        const int ma = 8 >> pa_[g], mb = 8 >> pb_[g];

        float phi = rot[3*g], th = rot[3*g+1], om = rot[3*g+2];
        float c, sn; __sincosf(0.5f*th, &sn, &c);
        float2 u00 = cscale(expi(-0.5f*(phi+om)),  c);
        float2 u01 = cscale(expi( 0.5f*(phi-om)), -sn);
        float2 u10 = cscale(expi(-0.5f*(phi-om)),  sn);
        float2 u11 = cscale(expi( 0.5f*(phi+om)),  c);
        float2 o = shflx(s, ma);
        s = (lane & ma) ? cadd(cmul(u10, o), cmul(u11, s))
                        : cadd(cmul(u00, s), cmul(u01, o));

        float cc, ss; __sincosf(0.5f*crx[g], &ss, &cc);
        o = shflx(s, mb);
        if (lane & ma) s = make_float2(cc*s.x + ss*o.y, cc*s.y - ss*o.x);

        o = shflx(s, mb);
        if (lane & ma) s = o;
    }
    return s;
}

// 544 threads: groups 0-15 -> U_q columns, 16-31 -> U_v columns, 32 -> k circuit,
// 33 -> dummy (k params, keeps warp 16 uniform). Main phase: threads 0-511, 128 samples.
__global__ void __launch_bounds__(544)
qc_kernel(const float* __restrict__ x1, const float* __restrict__ pre_w,
          const float* __restrict__ pre_b,
          const float* __restrict__ q_rot, const float* __restrict__ k_rot,
          const float* __restrict__ v_rot,
          const float* __restrict__ q_crx, const float* __restrict__ k_crx,
          const float* __restrict__ v_crx,
          const float* __restrict__ ln_w, const float* __restrict__ ln_b,
          const float* __restrict__ head_w, const float* __restrict__ head_b,
          float* __restrict__ out, int B)
{
    __shared__ float2 sUq[256];   // [col*16 + row]
    __shared__ float2 sUv[256];
    __shared__ float  sW[384];    // pre_w row-major [4][96]
    __shared__ float  sKx[4];
    __shared__ float  sPB[4];
    __shared__ float  sLnW[8], sLnB[8], sHW[16], sHB[2];

    int t = threadIdx.x;

    // small params
    for (int i = t; i < 384; i += 544) sW[i] = pre_w[i];
    if (t < 4)              sPB[t]     = pre_b[t];
    if (t >= 4 && t < 12)   sLnW[t-4]  = ln_w[t-4];
    if (t >= 12 && t < 20)  sLnB[t-12] = ln_b[t-12];
    if (t >= 20 && t < 36)  sHW[t-20]  = head_w[t-20];
    if (t >= 36 && t < 38)  sHB[t-36]  = head_b[t-36];

    // ---- parallel setup: one sim16 chain per 16-lane group ----
    {
        int grp  = t >> 4;      // 0..33
        int lane = t & 15;
        const float* rot; const float* crx; int col;
        if (grp < 16)      { rot = q_rot; crx = q_crx; col = grp;      }
        else if (grp < 32) { rot = v_rot; crx = v_crx; col = grp - 16; }
        else               { rot = k_rot; crx = k_crx; col = 0;        }

        float2 s = sim16(rot, crx, col, lane);

        if (grp < 16)       sUq[grp*16 + lane] = s;
        else if (grp < 32)  sUv[(grp-16)*16 + lane] = s;
        else {
            // <X_w> of the k state (groups 32,33 hold identical data; 16-lane-local shfls)
            #pragma unroll
            for (int w = 0; w < 4; w++){
                int mmk = 8 >> w;
                float2 o = shflx(s, mmk);
                float v = s.x*o.x + s.y*o.y;
                v += __shfl_xor_sync(0xffffffffu, v, 1);
                v += __shfl_xor_sync(0xffffffffu, v, 2);
                v += __shfl_xor_sync(0xffffffffu, v, 4);
                v += __shfl_xor_sync(0xffffffffu, v, 8);
                if (grp == 32 && lane == 0) sKx[w] = v;
            }
        }
    }
    __syncthreads();

    // ---- main phase: threads 0-511, 4 lanes per sample ----
    if (t >= 512) return;
    int s_idx = blockIdx.x * 128 + (t >> 2);
    int l     = t & 3;                       // quad lane: rows 4l..4l+3
    if (s_idx >= B) return;

    const float4* sW4  = (const float4*)sW;
    const float4* sUq4 = (const float4*)sUq;
    const float4* sUv4 = (const float4*)sUv;

    // x = x1[s] @ pre_w.T + pre_b  (each lane does 24 of 96, butterfly-reduce)
    float a0 = 0.f, a1 = 0.f, a2 = 0.f, a3 = 0.f;
    {
        const float4* row = (const float4*)(x1 + (size_t)s_idx * 96) + l * 6;
        #pragma unroll
        for (int k = 0; k < 6; k++){
            float4 v = row[k];
            float4 w0 = sW4[      l*6 + k];
            float4 w1 = sW4[ 24 + l*6 + k];
            float4 w2 = sW4[ 48 + l*6 + k];
            float4 w3 = sW4[ 72 + l*6 + k];
            a0 += v.x*w0.x + v.y*w0.y + v.z*w0.z + v.w*w0.w;
            a1 += v.x*w1.x + v.y*w1.y + v.z*w1.z + v.w*w1.w;
            a2 += v.x*w2.x + v.y*w2.y + v.z*w2.z + v.w*w2.w;
            a3 += v.x*w3.x + v.y*w3.y + v.z*w3.z + v.w*w3.w;
        }
        #pragma unroll
        for (int d = 1; d <= 2; d <<= 1){
            a0 += __shfl_xor_sync(0xffffffffu, a0, d);
            a1 += __shfl_xor_sync(0xffffffffu, a1, d);
            a2 += __shfl_xor_sync(0xffffffffu, a2, d);
            a3 += __shfl_xor_sync(0xffffffffu, a3, d);
        }
    }
    float xw[4] = { a0 + sPB[0], a1 + sPB[1], a2 + sPB[2], a3 + sPB[3] };

    float hc[4], hs[4];
    #pragma unroll
    for (int w = 0; w < 4; w++) __sincosf(0.5f * xw[w], &hs[w], &hc[w]);

    // product state magnitudes, (-1) of (-i)^popc folded in
    float m[16];
    #pragma unroll
    for (int i = 0; i < 16; i++){
        float v = ((i&8)?hs[0]:hc[0]) * ((i&4)?hs[1]:hc[1]) * ((i&2)?hs[2]:hc[2]) * ((i&1)?hs[3]:hc[3]);
        m[i] = (__popc(i) & 2) ? -v : v;
    }

    // ---- both matvecs (rows 4l..4l+3 of U_q*p and U_v*p) ----
    float2 stq[4], stv[4];
    #pragma unroll
    for (int r = 0; r < 4; r++){ stq[r] = make_float2(0.f,0.f); stv[r] = make_float2(0.f,0.f); }
    #pragma unroll
    for (int j = 0; j < 16; j++){
        float mj = m[j];
        float4 q0 = sUq4[j*8 + 2*l], q1 = sUq4[j*8 + 2*l + 1];
        float4 v0 = sUv4[j*8 + 2*l], v1 = sUv4[j*8 + 2*l + 1];
        if ((0x6996 >> j) & 1){   // odd parity: * (-i)
            stq[0].x += q0.y*mj; stq[0].y -= q0.x*mj;
            stq[1].x += q0.w*mj; stq[1].y -= q0.z*mj;
            stq[2].x += q1.y*mj; stq[2].y -= q1.x*mj;
            stq[3].x += q1.w*mj; stq[3].y -= q1.z*mj;
            stv[0].x += v0.y*mj; stv[0].y -= v0.x*mj;
            stv[1].x += v0.w*mj; stv[1].y -= v0.z*mj;
            stv[2].x += v1.y*mj; stv[2].y -= v1.x*mj;
            stv[3].x += v1.w*mj; stv[3].y -= v1.z*mj;
        } else {
            stq[0].x += q0.x*mj; stq[0].y += q0.y*mj;
            stq[1].x += q0.z*mj; stq[1].y += q0.w*mj;
            stq[2].x += q1.x*mj; stq[2].y += q1.y*mj;
            stq[3].x += q1.z*mj; stq[3].y += q1.w*mj;
            stv[0].x += v0.x*mj; stv[0].y += v0.y*mj;
            stv[1].x += v0.z*mj; stv[1].y += v0.w*mj;
            stv[2].x += v1.x*mj; stv[2].y += v1.y*mj;
            stv[3].x += v1.z*mj; stv[3].y += v1.w*mj;
        }
    }

    // ---- q path: RX(x) layer (symmetric pair update) ----
    #pragma unroll
    for (int w = 0; w < 2; w++){
        int d = 2 >> w;   // wire0: partner l^2, wire1: partner l^1
        float c = hc[w], s = hs[w];
        #pragma unroll
        for (int r = 0; r < 4; r++){
            float2 o = shflx(stq[r], d);
            stq[r] = make_float2(c*stq[r].x + s*o.y, c*stq[r].y - s*o.x);
        }
    }
    {   // wire2 (bit1): rows r <-> r^2
        float c = hc[2], s = hs[2];
        float2 n0 = make_float2(c*stq[0].x + s*stq[2].y, c*stq[0].y - s*stq[2].x);
        float2 n2 = make_float2(c*stq[2].x + s*stq[0].y, c*stq[2].y - s*stq[0].x);
        float2 n1 = make_float2(c*stq[1].x + s*stq[3].y, c*stq[1].y - s*stq[3].x);
        float2 n3 = make_float2(c*stq[3].x + s*stq[1].y, c*stq[3].y - s*stq[1].x);
        stq[0]=n0; stq[1]=n1; stq[2]=n2; stq[3]=n3;
    }
    {   // wire3 (bit0): rows r <-> r^1
        float c = hc[3], s = hs[3];
        float2 n0 = make_float2(c*stq[0].x + s*stq[1].y, c*stq[0].y - s*stq[1].x);
        float2 n1 = make_float2(c*stq[1].x + s*stq[0].y, c*stq[1].y - s*stq[0].x);
        float2 n2 = make_float2(c*stq[2].x + s*stq[3].y, c*stq[2].y - s*stq[3].x);
        float2 n3 = make_float2(c*stq[3].x + s*stq[2].y, c*stq[3].y - s*stq[2].x);
        stq[0]=n0; stq[1]=n1; stq[2]=n2; stq[3]=n3;
    }

    // ---- scores ----
    float n0 = stq[0].x*stq[0].x + stq[0].y*stq[0].y;
    float n1 = stq[1].x*stq[1].x + stq[1].y*stq[1].y;
    float n2 = stq[2].x*stq[2].x + stq[2].y*stq[2].y;
    float n3 = stq[3].x*stq[3].x + stq[3].y*stq[3].y;
    float nsum = n0 + n1 + n2 + n3;
    float z0 = (l & 2) ? -nsum : nsum;
    float z1 = (l & 1) ? -nsum : nsum;
    float z2 = n0 + n1 - n2 - n3;
    float z3 = n0 - n1 + n2 - n3;

    float x0 = 0.f, x1m = 0.f;
    #pragma unroll
    for (int r = 0; r < 4; r++){
        float2 o = shflx(stq[r], 2);
        x0 += stq[r].x*o.x + stq[r].y*o.y;
    }
    #pragma unroll
    for (int r = 0; r < 4; r++){
        float2 o = shflx(stq[r], 1);
        x1m += stq[r].x*o.x + stq[r].y*o.y;
    }
    float x2 = 2.f*(stq[0].x*stq[2].x + stq[0].y*stq[2].y + stq[1].x*stq[3].x + stq[1].y*stq[3].y);
    float x3 = 2.f*(stq[0].x*stq[1].x + stq[0].y*stq[1].y + stq[2].x*stq[3].x + stq[2].y*stq[3].y);

    #pragma unroll
    for (int d = 1; d <= 2; d <<= 1){
        z0 += __shfl_xor_sync(0xffffffffu, z0, d);
        z1 += __shfl_xor_sync(0xffffffffu, z1, d);
        z2 += __shfl_xor_sync(0xffffffffu, z2, d);
        z3 += __shfl_xor_sync(0xffffffffu, z3, d);
        x0 += __shfl_xor_sync(0xffffffffu, x0, d);
        x1m+= __shfl_xor_sync(0xffffffffu, x1m, d);
        x2 += __shfl_xor_sync(0xffffffffu, x2, d);
        x3 += __shfl_xor_sync(0xffffffffu, x3, d);
    }
    x0 *= sKx[0]; x1m *= sKx[1]; x2 *= sKx[2]; x3 *= sKx[3];

    float rz0 = fast_tanh(sqrtf(z0*z0 + x0*x0))   * (0.5f * PI_F);
    float rz1 = fast_tanh(sqrtf(z1*z1 + x1m*x1m)) * (0.5f * PI_F);
    float rz2 = fast_tanh(sqrtf(z2*z2 + x2*x2))   * (0.5f * PI_F);
    float rz3 = fast_tanh(sqrtf(z3*z3 + x3*x3))   * (0.5f * PI_F);

    // ---- v path: RZ phases ----
    float phl = ((l & 2) ? rz0 : -rz0) + ((l & 1) ? rz1 : -rz1);
    #pragma unroll
    for (int r = 0; r < 4; r++){
        float ph = phl + ((r & 2) ? rz2 : -rz2) + ((r & 1) ? rz3 : -rz3);
        float sp, cp; __sincosf(ph, &sp, &cp);
        stv[r] = make_float2(stv[r].x*cp - stv[r].y*sp, stv[r].x*sp + stv[r].y*cp);
    }
    // CNOT(0,1): lanes with bit l&2 take partner (l^1)'s value
    #pragma unroll
    for (int r = 0; r < 4; r++){
        float2 o = shflx(stv[r], 1);
        if (l & 2) stv[r] = o;
    }
    // CNOT(1,2): if (l&1): swap rows r <-> r^2
    if (l & 1){
        float2 tq = stv[0]; stv[0] = stv[2]; stv[2] = tq;
        tq = stv[1]; stv[1] = stv[3]; stv[3] = tq;
    }
    // CNOT(2,3): swap rows 2,3
    { float2 tq = stv[2]; stv[2] = stv[3]; stv[3] = tq; }

    // ---- final expectations ----
    float q0n = stv[0].x*stv[0].x + stv[0].y*stv[0].y;
    float q1n = stv[1].x*stv[1].x + stv[1].y*stv[1].y;
    float q2n = stv[2].x*stv[2].x + stv[2].y*stv[2].y;
    float q3n = stv[3].x*stv[3].x + stv[3].y*stv[3].y;
    float qs = q0n + q1n + q2n + q3n;
    float o0 = (l & 2) ? -qs : qs;
    float o1 = (l & 1) ? -qs : qs;
    float o2 = q0n + q1n - q2n - q3n;
    float o3 = q0n - q1n + q2n - q3n;

    float o4 = 0.f, o5 = 0.f;
    #pragma unroll
    for (int r = 0; r < 4; r++){
        float2 o = shflx(stv[r], 2);
        o4 += stv[r].x*o.x + stv[r].y*o.y;
    }
    #pragma unroll
    for (int r = 0; r < 4; r++){
        float2 o = shflx(stv[r], 1);
        o5 += stv[r].x*o.x + stv[r].y*o.y;
    }
    float o6 = 2.f*(stv[0].x*stv[2].x + stv[0].y*stv[2].y + stv[1].x*stv[3].x + stv[1].y*stv[3].y);
    float o7 = 2.f*(stv[0].x*stv[1].x + stv[0].y*stv[1].y + stv[2].x*stv[3].x + stv[2].y*stv[3].y);

    #pragma unroll
    for (int d = 1; d <= 2; d <<= 1){
        o0 += __shfl_xor_sync(0xffffffffu, o0, d);
        o1 += __shfl_xor_sync(0xffffffffu, o1, d);
        o2 += __shfl_xor_sync(0xffffffffu, o2, d);
        o3 += __shfl_xor_sync(0xffffffffu, o3, d);
        o4 += __shfl_xor_sync(0xffffffffu, o4, d);
        o5 += __shfl_xor_sync(0xffffffffu, o5, d);
        o6 += __shfl_xor_sync(0xffffffffu, o6, d);
        o7 += __shfl_xor_sync(0xffffffffu, o7, d);
    }

    if (l == 0){
        float o[8] = { o0, o1, o2, o3, o4, o5, o6, o7 };
        float mu = 0.f;
        #pragma unroll
        for (int k = 0; k < 8; k++) mu += o[k];
        mu *= 0.125f;
        float var = 0.f;
        #pragma unroll
        for (int k = 0; k < 8; k++){ float dd = o[k] - mu; var += dd * dd; }
        var *= 0.125f;
        float inv = rsqrtf(var + 1e-5f);

        float r0 = sHB[0], r1 = sHB[1];
        #pragma unroll
        for (int k = 0; k < 8; k++){
            float y = (o[k] - mu) * inv * sLnW[k] + sLnB[k];
            float g = 0.5f * y * (1.f + erff(y * 0.70710678118654752f));
            r0 += g * sHW[k];
            r1 += g * sHW[8 + k];
        }
        ((float2*)out)[s_idx] = make_float2(r0, r1);
    }
}

extern "C" void kernel_launch(void* const* d_in, const int* in_sizes, int n_in,
                              void* d_out, int out_size)
{
    const float* x1     = (const float*)d_in[0];
    const float* pre_w  = (const float*)d_in[1];
    const float* pre_b  = (const float*)d_in[2];
    const float* q_rot  = (const float*)d_in[3];
    const float* k_rot  = (const float*)d_in[4];
    const float* v_rot  = (const float*)d_in[5];
    const float* q_crx  = (const float*)d_in[6];
    const float* k_crx  = (const float*)d_in[7];
    const float* v_crx  = (const float*)d_in[8];
    const float* ln_w   = (const float*)d_in[9];
    const float* ln_b   = (const float*)d_in[10];
    const float* head_w = (const float*)d_in[11];
    const float* head_b = (const float*)d_in[12];

    int B = in_sizes[0] / 96;
    int blocks = (B + 127) / 128;

    qc_kernel<<<blocks, 544>>>(x1, pre_w, pre_b, q_rot, k_rot, v_rot,
                               q_crx, k_crx, v_crx, ln_w, ln_b, head_w, head_b,
                               (float*)d_out, B);
}